// round 1
// baseline (speedup 1.0000x reference)
#include <cuda_runtime.h>
#include <math.h>

#define TT 32
#define NN 1024
#define FF 64
#define HH 128
#define H4 512

// ---- scratch (static __device__ arrays; no allocation at runtime) ----
__device__ float g_xs[TT * NN * HH];          // 16 MB: xs = x @ Win^T + b
__device__ float g_msgp[2][2][NN * HH];       // split-K partials of adj @ h_time
__device__ float g_base[2][NN * H4];          // xt@Wx + msg@Wn + b (per step)
__device__ float g_H0[2][NN * HH];            // h_time / final layer output
__device__ float g_C0[2][NN * HH];
__device__ float g_H1[2][NN * HH];            // layer-1 output
__device__ float g_C1[2][NN * HH];
__device__ float g_v[2 * HH + 1];             // fused fc0/wout vector + scalar bias

__device__ __forceinline__ float sigm(float x) { return 1.0f / (1.0f + expf(-x)); }

// ============================================================
// P1: xs[t,n,h] = sum_f x[t,n,f] * Win_w[h,f] + Win_b[h]
// tile 64x64, K=64. grid (2, 512), 256 threads.
// ============================================================
__global__ void k_xs(const float* __restrict__ x,
                     const float* __restrict__ Ww,
                     const float* __restrict__ Wb) {
    __shared__ float As[16][68];
    __shared__ float Bs[16][64];
    int tid = threadIdx.x;
    int tx = tid & 15, ty = tid >> 4;
    int m0 = blockIdx.y * 64;
    int n0 = blockIdx.x * 64;
    float acc[4][4] = {};
    int arow = tid >> 2;
    int akq  = (tid & 3) * 4;
    int bn   = tid & 63;
    int bkq  = (tid >> 6) * 4;
    for (int k0 = 0; k0 < FF; k0 += 16) {
        float4 av = *(const float4*)&x[(size_t)(m0 + arow) * FF + k0 + akq];
        As[akq + 0][arow] = av.x; As[akq + 1][arow] = av.y;
        As[akq + 2][arow] = av.z; As[akq + 3][arow] = av.w;
        // B[k][n] = Win_w[n0+n][k0+k]  (transposed read of (H,F) row-major)
        float4 bv = *(const float4*)&Ww[(size_t)(n0 + bn) * FF + k0 + bkq];
        Bs[bkq + 0][bn] = bv.x; Bs[bkq + 1][bn] = bv.y;
        Bs[bkq + 2][bn] = bv.z; Bs[bkq + 3][bn] = bv.w;
        __syncthreads();
#pragma unroll
        for (int kk = 0; kk < 16; kk++) {
            float4 b4 = *(const float4*)&Bs[kk][tx * 4];
            float a0 = As[kk][ty * 4 + 0], a1 = As[kk][ty * 4 + 1];
            float a2 = As[kk][ty * 4 + 2], a3 = As[kk][ty * 4 + 3];
            acc[0][0] += a0 * b4.x; acc[0][1] += a0 * b4.y; acc[0][2] += a0 * b4.z; acc[0][3] += a0 * b4.w;
            acc[1][0] += a1 * b4.x; acc[1][1] += a1 * b4.y; acc[1][2] += a1 * b4.z; acc[1][3] += a1 * b4.w;
            acc[2][0] += a2 * b4.x; acc[2][1] += a2 * b4.y; acc[2][2] += a2 * b4.z; acc[2][3] += a2 * b4.w;
            acc[3][0] += a3 * b4.x; acc[3][1] += a3 * b4.y; acc[3][2] += a3 * b4.z; acc[3][3] += a3 * b4.w;
        }
        __syncthreads();
    }
#pragma unroll
    for (int r = 0; r < 4; r++) {
        int m = m0 + ty * 4 + r;
#pragma unroll
        for (int c = 0; c < 4; c++) {
            int n = n0 + tx * 4 + c;
            g_xs[(size_t)m * HH + n] = acc[r][c] + Wb[n];
        }
    }
}

// ============================================================
// init: H0 = C0 = first frame of each direction's sequence
// ============================================================
__global__ void k_init() {
    int i = blockIdx.x * blockDim.x + threadIdx.x;   // 2*N*H total
    int d = i / (NN * HH);
    int r = i - d * (NN * HH);
    int t0 = d ? (TT - 1) : 0;
    float v = g_xs[(size_t)t0 * NN * HH + r];
    g_H0[d][r] = v;
    g_C0[d][r] = v;
}

// ============================================================
// prep: v[j] = sum_k wout_w[k] * fc0_w[k][j];  v[256] = scalar bias
// ============================================================
__global__ void k_prep(const float* __restrict__ fc0w,
                       const float* __restrict__ fc0b,
                       const float* __restrict__ woutw,
                       const float* __restrict__ woutb) {
    int j = threadIdx.x;
    if (j < 2 * HH) {
        float s = 0.0f;
        for (int k = 0; k < HH; k++) s += woutw[k] * fc0w[(size_t)k * (2 * HH) + j];
        g_v[j] = s;
    } else if (j == 2 * HH) {
        float s = woutb[0];
        for (int k = 0; k < HH; k++) s += woutw[k] * fc0b[k];
        g_v[2 * HH] = s;
    }
}

// ============================================================
// K1: msg partials = adj_t @ H0   (split-K = 2)
// C (1024 x 128) tile 64x64.  grid (2, 16, 4): z = dir*2 + ksplit
// ============================================================
__global__ void k_msg(const float* __restrict__ adjs, int s) {
    int z = blockIdx.z;
    int d = z >> 1, ks = z & 1;
    int t = d ? (TT - 1 - s) : s;
    const float* __restrict__ A = adjs + (size_t)t * NN * NN;
    const float* __restrict__ B = g_H0[d];

    __shared__ float As[16][68];
    __shared__ float Bs[16][64];
    int tid = threadIdx.x;
    int tx = tid & 15, ty = tid >> 4;
    int m0 = blockIdx.y * 64;
    int n0 = blockIdx.x * 64;
    float acc[4][4] = {};
    int arow = tid >> 2;
    int akq  = (tid & 3) * 4;
    int bk   = tid >> 4;
    int bn4  = (tid & 15) * 4;
    int kbeg = ks * 512;
    for (int k0 = kbeg; k0 < kbeg + 512; k0 += 16) {
        float4 av = *(const float4*)&A[(size_t)(m0 + arow) * NN + k0 + akq];
        As[akq + 0][arow] = av.x; As[akq + 1][arow] = av.y;
        As[akq + 2][arow] = av.z; As[akq + 3][arow] = av.w;
        float4 bv = *(const float4*)&B[(size_t)(k0 + bk) * HH + n0 + bn4];
        *(float4*)&Bs[bk][bn4] = bv;
        __syncthreads();
#pragma unroll
        for (int kk = 0; kk < 16; kk++) {
            float4 b4 = *(const float4*)&Bs[kk][tx * 4];
            float a0 = As[kk][ty * 4 + 0], a1 = As[kk][ty * 4 + 1];
            float a2 = As[kk][ty * 4 + 2], a3 = As[kk][ty * 4 + 3];
            acc[0][0] += a0 * b4.x; acc[0][1] += a0 * b4.y; acc[0][2] += a0 * b4.z; acc[0][3] += a0 * b4.w;
            acc[1][0] += a1 * b4.x; acc[1][1] += a1 * b4.y; acc[1][2] += a1 * b4.z; acc[1][3] += a1 * b4.w;
            acc[2][0] += a2 * b4.x; acc[2][1] += a2 * b4.y; acc[2][2] += a2 * b4.z; acc[2][3] += a2 * b4.w;
            acc[3][0] += a3 * b4.x; acc[3][1] += a3 * b4.y; acc[3][2] += a3 * b4.z; acc[3][3] += a3 * b4.w;
        }
        __syncthreads();
    }
    float* __restrict__ C = g_msgp[d][ks];
#pragma unroll
    for (int r = 0; r < 4; r++) {
        int m = m0 + ty * 4 + r;
#pragma unroll
        for (int c = 0; c < 4; c++) C[(size_t)m * HH + n0 + tx * 4 + c] = acc[r][c];
    }
}

// ============================================================
// K2: base = [xs_t | (msgp0+msgp1)] @ [Wx ; Wn] + b    K = 256
// C (1024 x 512) tile 64x64.  grid (8, 16, 2): z = dir
// ============================================================
__global__ void k_base(const float* __restrict__ fWx, const float* __restrict__ fWn,
                       const float* __restrict__ fb,
                       const float* __restrict__ bWx, const float* __restrict__ bWn,
                       const float* __restrict__ bb, int s) {
    int d = blockIdx.z;
    int t = d ? (TT - 1 - s) : s;
    const float* __restrict__ Wx = d ? bWx : fWx;
    const float* __restrict__ Wn = d ? bWn : fWn;
    const float* __restrict__ bias = d ? bb : fb;
    const float* __restrict__ Xs  = g_xs + (size_t)t * NN * HH;
    const float* __restrict__ M0  = g_msgp[d][0];
    const float* __restrict__ M1  = g_msgp[d][1];

    __shared__ float As[16][68];
    __shared__ float Bs[16][64];
    int tid = threadIdx.x;
    int tx = tid & 15, ty = tid >> 4;
    int m0 = blockIdx.y * 64;
    int n0 = blockIdx.x * 64;
    float acc[4][4] = {};
    int arow = tid >> 2;
    int akq  = (tid & 3) * 4;
    int bk   = tid >> 4;
    int bn4  = (tid & 15) * 4;
    for (int k0 = 0; k0 < 256; k0 += 16) {
        int kg = k0 + akq;
        float4 av;
        if (kg < HH) {
            av = *(const float4*)&Xs[(size_t)(m0 + arow) * HH + kg];
        } else {
            int kr = kg - HH;
            float4 p0 = *(const float4*)&M0[(size_t)(m0 + arow) * HH + kr];
            float4 p1 = *(const float4*)&M1[(size_t)(m0 + arow) * HH + kr];
            av.x = p0.x + p1.x; av.y = p0.y + p1.y; av.z = p0.z + p1.z; av.w = p0.w + p1.w;
        }
        As[akq + 0][arow] = av.x; As[akq + 1][arow] = av.y;
        As[akq + 2][arow] = av.z; As[akq + 3][arow] = av.w;
        int kb = k0 + bk;
        const float* __restrict__ W = (kb < HH) ? (Wx + (size_t)kb * H4)
                                                : (Wn + (size_t)(kb - HH) * H4);
        *(float4*)&Bs[bk][bn4] = *(const float4*)&W[n0 + bn4];
        __syncthreads();
#pragma unroll
        for (int kk = 0; kk < 16; kk++) {
            float4 b4 = *(const float4*)&Bs[kk][tx * 4];
            float a0 = As[kk][ty * 4 + 0], a1 = As[kk][ty * 4 + 1];
            float a2 = As[kk][ty * 4 + 2], a3 = As[kk][ty * 4 + 3];
            acc[0][0] += a0 * b4.x; acc[0][1] += a0 * b4.y; acc[0][2] += a0 * b4.z; acc[0][3] += a0 * b4.w;
            acc[1][0] += a1 * b4.x; acc[1][1] += a1 * b4.y; acc[1][2] += a1 * b4.z; acc[1][3] += a1 * b4.w;
            acc[2][0] += a2 * b4.x; acc[2][1] += a2 * b4.y; acc[2][2] += a2 * b4.z; acc[2][3] += a2 * b4.w;
            acc[3][0] += a3 * b4.x; acc[3][1] += a3 * b4.y; acc[3][2] += a3 * b4.z; acc[3][3] += a3 * b4.w;
        }
        __syncthreads();
    }
    float* __restrict__ C = g_base[d];
#pragma unroll
    for (int r = 0; r < 4; r++) {
        int m = m0 + ty * 4 + r;
#pragma unroll
        for (int c = 0; c < 4; c++) {
            int n = n0 + tx * 4 + c;
            C[(size_t)m * H4 + n] = acc[r][c] + bias[n];
        }
    }
}

// ============================================================
// K3: z = base + Hin @ Wh, fused LSTM gate epilogue.
// Gate-aligned tiling: block covers 64 rows x 16 h-cols, i.e. z columns
// { g*128 + bh + j : g<4, j<16 }. Each thread owns all 4 gates for
// (4 rows, 1 h) -> full cell update in registers.
// grid (8, 16, 2): x = h-block, z = dir.  layer: 0 = H0->H1, 1 = H1->H0
// ============================================================
__global__ void k_cell(const float* __restrict__ fWh, const float* __restrict__ bWh,
                       int layer) {
    int d = blockIdx.z;
    const float* __restrict__ Wh  = d ? bWh : fWh;
    const float* __restrict__ Hin = layer ? g_H1[d] : g_H0[d];
    const float* __restrict__ Cin = layer ? g_C1[d] : g_C0[d];
    float* __restrict__ Hout = layer ? g_H0[d] : g_H1[d];
    float* __restrict__ Cout = layer ? g_C0[d] : g_C1[d];
    const float* __restrict__ base = g_base[d];

    __shared__ float As[16][68];
    __shared__ float Bs[16][64];      // Bs[k][j*4 + g] = Wh[k][g*128 + bh + j]
    int tid = threadIdx.x;
    int tx = tid & 15, ty = tid >> 4;
    int m0 = blockIdx.y * 64;
    int bh = blockIdx.x * 16;
    float acc[4][4] = {};
    int arow = tid >> 2;
    int akq  = (tid & 3) * 4;
    int bk   = tid >> 4;
    int bq   = tid & 15;
    for (int k0 = 0; k0 < HH; k0 += 16) {
        float4 av = *(const float4*)&Hin[(size_t)(m0 + arow) * HH + k0 + akq];
        As[akq + 0][arow] = av.x; As[akq + 1][arow] = av.y;
        As[akq + 2][arow] = av.z; As[akq + 3][arow] = av.w;
#pragma unroll
        for (int g = 0; g < 4; g++)
            Bs[bk][bq * 4 + g] = Wh[(size_t)(k0 + bk) * H4 + g * HH + bh + bq];
        __syncthreads();
#pragma unroll
        for (int kk = 0; kk < 16; kk++) {
            float4 b4 = *(const float4*)&Bs[kk][tx * 4];
            float a0 = As[kk][ty * 4 + 0], a1 = As[kk][ty * 4 + 1];
            float a2 = As[kk][ty * 4 + 2], a3 = As[kk][ty * 4 + 3];
            acc[0][0] += a0 * b4.x; acc[0][1] += a0 * b4.y; acc[0][2] += a0 * b4.z; acc[0][3] += a0 * b4.w;
            acc[1][0] += a1 * b4.x; acc[1][1] += a1 * b4.y; acc[1][2] += a1 * b4.z; acc[1][3] += a1 * b4.w;
            acc[2][0] += a2 * b4.x; acc[2][1] += a2 * b4.y; acc[2][2] += a2 * b4.z; acc[2][3] += a2 * b4.w;
            acc[3][0] += a3 * b4.x; acc[3][1] += a3 * b4.y; acc[3][2] += a3 * b4.z; acc[3][3] += a3 * b4.w;
        }
        __syncthreads();
    }
    int h = bh + tx;
#pragma unroll
    for (int r = 0; r < 4; r++) {
        int m = m0 + ty * 4 + r;
        float zi = acc[r][0] + base[(size_t)m * H4 + 0 * HH + h];
        float zf = acc[r][1] + base[(size_t)m * H4 + 1 * HH + h];
        float zo = acc[r][2] + base[(size_t)m * H4 + 2 * HH + h];
        float zg = acc[r][3] + base[(size_t)m * H4 + 3 * HH + h];
        float c_old = Cin[(size_t)m * HH + h];
        float c2 = sigm(zf) * c_old + sigm(zi) * tanhf(zg);
        float h2 = sigm(zo) * tanhf(c2);
        Cout[(size_t)m * HH + h] = c2;
        Hout[(size_t)m * HH + h] = h2;
    }
}

// ============================================================
// final: y[n] = [h_f | h_b][n] . v + v[256]
// ============================================================
__global__ void k_final(float* __restrict__ out) {
    int warp = threadIdx.x >> 5;
    int lane = threadIdx.x & 31;
    int n = blockIdx.x * 8 + warp;
    float s = 0.0f;
#pragma unroll
    for (int j = lane; j < 2 * HH; j += 32) {
        float hv = (j < HH) ? g_H0[0][(size_t)n * HH + j]
                            : g_H0[1][(size_t)n * HH + (j - HH)];
        s += hv * g_v[j];
    }
#pragma unroll
    for (int o = 16; o > 0; o >>= 1) s += __shfl_down_sync(0xffffffffu, s, o);
    if (lane == 0) out[n] = s + g_v[2 * HH];
}

// ============================================================
extern "C" void kernel_launch(void* const* d_in, const int* in_sizes, int n_in,
                              void* d_out, int out_size) {
    const float* x     = (const float*)d_in[0];
    const float* adjs  = (const float*)d_in[1];
    // d_in[2] = edgenum (unused by reference math)
    const float* Winw  = (const float*)d_in[3];
    const float* Winb  = (const float*)d_in[4];
    const float* fWx   = (const float*)d_in[5];
    const float* fWh   = (const float*)d_in[6];
    const float* fWn   = (const float*)d_in[7];
    const float* fb    = (const float*)d_in[8];
    const float* bWx   = (const float*)d_in[9];
    const float* bWh   = (const float*)d_in[10];
    const float* bWn   = (const float*)d_in[11];
    const float* bb    = (const float*)d_in[12];
    const float* fc0w  = (const float*)d_in[13];
    const float* fc0b  = (const float*)d_in[14];
    const float* woutw = (const float*)d_in[15];
    const float* woutb = (const float*)d_in[16];
    float* out = (float*)d_out;

    // xs = x @ Win^T + b   (32768 x 128, K=64)
    k_xs<<<dim3(2, 512), 256>>>(x, Winw, Winb);
    // fused fc0/wout vector
    k_prep<<<1, 288>>>(fc0w, fc0b, woutw, woutb);
    // carries: h_time = c_time = xs[first frame of each direction]
    k_init<<<(2 * NN * HH) / 256, 256>>>();

    for (int s = 0; s < TT; s++) {
        k_msg <<<dim3(2, 16, 4), 256>>>(adjs, s);
        k_base<<<dim3(8, 16, 2), 256>>>(fWx, fWn, fb, bWx, bWn, bb, s);
        k_cell<<<dim3(8, 16, 2), 256>>>(fWh, bWh, 0);  // layer 1: H0 -> H1
        k_cell<<<dim3(8, 16, 2), 256>>>(fWh, bWh, 1);  // layer 2: H1 -> H0
    }

    k_final<<<NN / 8, 256>>>(out);
}